// round 11
// baseline (speedup 1.0000x reference)
#include <cuda_runtime.h>
#include <cstdint>
#include <cstddef>

// ============================================================================
//   z[8192,32] = relu( Gi2j@(xi Wi+bi) + Adj2j@(xj1 Wj1+bj1)
//                    + coAdj2j@(xj1 Wj2+bj2) + Gk2j@(xk Wk+bk) )
// Inputs (metadata order):
//   0 xi, 1 xj1, 2 xj2(unused), 3 xk, 4 Gi2j, 5 Adj2j, 6 coAdj2j, 7 Gk2j,
//   8..11 W_i,W_j1,W_j2,W_k, 12..15 b_i,b_j1,b_j2,b_k
//
// Bench PTX target is plain sm_103 (no 'a' features): no tcgen05/TMEM.
// R11: A-prologue issued BEFORE the fused prep (prep compute + flag handshake
// hidden under the first 144KB of A DRAM fetch); B for stages 0-1 fetched
// after the flags (L2-resident). Mainloop = proven R7 structure.
// ============================================================================

// Scratch (allocation-free: __device__ globals; zero-initialized at load)
__device__ float g_B[4 * 32 * 8192];        // [branch][c][k]  (Y_m^T, k-contiguous)
__device__ float g_partial[4 * 8192 * 32];  // [branch][j][c]
__device__ unsigned int g_flag[128];        // [branch*32 + mtile] B-slice ready

__device__ __forceinline__ uint32_t smem_u32(const void* p) {
    uint32_t a;
    asm("{ .reg .u64 t; cvta.to.shared.u64 t, %1; cvt.u32.u64 %0, t; }" : "=r"(a) : "l"(p));
    return a;
}

#define CP_ASYNC16(dst, src) \
    asm volatile("cp.async.cg.shared.global [%0], [%1], 16;" :: "r"(dst), "l"(src) : "memory")
#define CP_COMMIT() asm volatile("cp.async.commit_group;" ::: "memory")
#define CP_WAIT1()  asm volatile("cp.async.wait_group 1;" ::: "memory")
#define CP_WAIT0()  asm volatile("cp.async.wait_group 0;" ::: "memory")

// ldmatrix: b16 view over fp32 data (each b16-pair = one fp32 element).
#define LDSM_X4(r0, r1, r2, r3, addr) \
    asm volatile("ldmatrix.sync.aligned.m8n8.x4.shared.b16 {%0,%1,%2,%3}, [%4];" \
        : "=r"(r0), "=r"(r1), "=r"(r2), "=r"(r3) : "r"(addr))
#define LDSM_X2(r0, r1, addr) \
    asm volatile("ldmatrix.sync.aligned.m8n8.x2.shared.b16 {%0,%1}, [%2];" \
        : "=r"(r0), "=r"(r1) : "r"(addr))

__device__ __forceinline__ void mma_tf32(float& c0, float& c1, float& c2, float& c3,
                                         uint32_t a0, uint32_t a1, uint32_t a2, uint32_t a3,
                                         uint32_t b0, uint32_t b1) {
    asm volatile(
        "mma.sync.aligned.m16n8k8.row.col.f32.tf32.tf32.f32 "
        "{%0,%1,%2,%3}, {%4,%5,%6,%7}, {%8,%9}, {%0,%1,%2,%3};"
        : "+f"(c0), "+f"(c1), "+f"(c2), "+f"(c3)
        : "r"(a0), "r"(a1), "r"(a2), "r"(a3), "r"(b0), "r"(b1));
}

// ============================================================================
// Fused prep + tf32 mma.sync GEMM
//   grid (32 M-tiles, 4 branches), 256 threads (8 warps; warp = m32 x n32).
//   Prologue: A cp.async for stages 0,1 FIRST; then prep this CTA's B slice
//   (k in [mtile*256,+256)) + flag handshake (hidden under the A fetch);
//   then B cp.async for stages 0,1; wait_group 0; mainloop.
// ============================================================================
#define M_TILE  256
#define S_STAGES 3
#define T_CHUNKS 128                 // 8192 / 64
#define ROW_BYTES 256                // 64 floats, no pad
#define A_BYTES (M_TILE * ROW_BYTES)          // 65536
#define B_OFF   A_BYTES
#define STAGE_BYTES (A_BYTES + 32 * ROW_BYTES)  // 73728
#define RING_BYTES (S_STAGES * STAGE_BYTES)     // 221184
#define PREP_OFF  RING_BYTES                    // Ws(4096) + bs(128)
#define SMEM_TOTAL (RING_BYTES + 4096 + 128)    // 225408 B (1 CTA/SM)

__device__ __forceinline__ void load_stage_A(uint32_t sbase, const float* __restrict__ G,
                                             int slot, int kchunk, int mtile, int tid)
{
    const int kbase = kchunk * 64;
    const uint32_t st = sbase + slot * STAGE_BYTES;
#pragma unroll
    for (int i = 0; i < 16; i++) {
        int ch = tid + i * 256;              // 0..4095
        int r = ch >> 4, u = ch & 15;
        uint32_t dst = st + r * ROW_BYTES + ((u ^ (r & 7)) << 4);
        const float* src = G + (size_t)(mtile * M_TILE + r) * 8192 + kbase + u * 4;
        CP_ASYNC16(dst, src);
    }
}

__device__ __forceinline__ void load_stage_B(uint32_t sbase, const float* __restrict__ B,
                                             int slot, int kchunk, int tid)
{
    const int kbase = kchunk * 64;
    const uint32_t st = sbase + slot * STAGE_BYTES;
#pragma unroll
    for (int i = 0; i < 2; i++) {
        int ch = tid + i * 256;              // 0..511
        int r = ch >> 4, u = ch & 15;
        uint32_t dst = st + B_OFF + r * ROW_BYTES + ((u ^ (r & 7)) << 4);
        const float* src = B + (size_t)r * 8192 + kbase + u * 4;
        CP_ASYNC16(dst, src);
    }
}

__global__ void __launch_bounds__(256, 1)
gemm_tf32_kernel(const float* __restrict__ G0, const float* __restrict__ G1,
                 const float* __restrict__ G2, const float* __restrict__ G3,
                 const float* __restrict__ xi, const float* __restrict__ xj1,
                 const float* __restrict__ xk,
                 const float* __restrict__ Wi, const float* __restrict__ Wj1,
                 const float* __restrict__ Wj2, const float* __restrict__ Wk,
                 const float* __restrict__ bi, const float* __restrict__ bj1,
                 const float* __restrict__ bj2, const float* __restrict__ bk)
{
    extern __shared__ __align__(256) char smem[];
    const uint32_t sbase = smem_u32(smem);
    const int tid = threadIdx.x;
    const int w = tid >> 5;        // 0..7 (warp owns rows w*32..w*32+31)
    const int lid = tid & 31;
    const int l4 = lid >> 2;       // 0..7
    const int lm = lid & 3;        // 0..3
    const int mtile = blockIdx.x;
    const int branch = blockIdx.y;
    const float* __restrict__ G =
        (branch == 0) ? G0 : (branch == 1) ? G1 : (branch == 2) ? G2 : G3;
    float* __restrict__ Bbr = g_B + (size_t)branch * 32 * 8192;

    // ---- Issue A fetches for stages 0,1 FIRST (DRAM busy during prep) ----
    load_stage_A(sbase, G, 0, 0, mtile, tid);
    CP_COMMIT();
    load_stage_A(sbase, G, 1, 1, mtile, tid);
    CP_COMMIT();

    // ---------------- Phase 0: prep this CTA's B slice ----------------
    {
        // branch 2 consumes xj1 with the j2 weights (faithful to source)
        const float* x = (branch == 0) ? xi : (branch == 3) ? xk : xj1;
        const float* W = (branch == 0) ? Wi : (branch == 1) ? Wj1
                         : (branch == 2) ? Wj2 : Wk;
        const float* b = (branch == 0) ? bi : (branch == 1) ? bj1
                         : (branch == 2) ? bj2 : bk;

        float* Ws = reinterpret_cast<float*>(smem + PREP_OFF);        // 1024 f
        float* bs = reinterpret_cast<float*>(smem + PREP_OFF) + 1024; // 32 f
#pragma unroll
        for (int i = 0; i < 4; i++) Ws[tid + i * 256] = W[tid + i * 256];
        if (tid < 32) bs[tid] = b[tid];
        __syncthreads();

        const int k = mtile * 256 + tid;     // this thread's k-row
        float xr[32];
        const float4* xrow = reinterpret_cast<const float4*>(x + (size_t)k * 32);
#pragma unroll
        for (int t = 0; t < 8; t++) {
            float4 v = xrow[t];
            xr[4 * t] = v.x; xr[4 * t + 1] = v.y; xr[4 * t + 2] = v.z; xr[4 * t + 3] = v.w;
        }
        float acc[32];
#pragma unroll
        for (int c = 0; c < 32; c++) acc[c] = bs[c];
#pragma unroll
        for (int t = 0; t < 32; t++) {
            const float xv = xr[t];
#pragma unroll
            for (int c = 0; c < 32; c++) acc[c] += xv * Ws[t * 32 + c];
        }
#pragma unroll
        for (int c = 0; c < 32; c++) {
            uint32_t v = __float_as_uint(acc[c]);
            asm volatile("cvt.rna.tf32.f32 %0, %0;" : "+r"(v));  // pre-round B
            Bbr[(size_t)c * 8192 + k] = __uint_as_float(v);      // coalesced in k
        }

        // Publish, then wait for all 32 slices of this branch.
        __threadfence();
        __syncthreads();
        if (tid == 0) atomicExch(&g_flag[branch * 32 + mtile], 1u);
        if (tid < 32) {
            while (atomicAdd(&g_flag[branch * 32 + tid], 0u) == 0u) { __nanosleep(64); }
        }
        __syncthreads();
        __threadfence();   // acquire side: B stores from other CTAs visible
    }

    // ---- B fetches for stages 0,1 (small; mostly L2 hits), drain all ----
    const float* __restrict__ B = Bbr;
    load_stage_B(sbase, B, 0, 0, tid);
    load_stage_B(sbase, B, 1, 1, tid);
    CP_COMMIT();
    CP_WAIT0();
    __syncthreads();

    // ---------------- Phase 1: GEMM mainloop (R7-proven) ----------------
    const int lrow8 = lid & 7;                   // swizzle XOR for this thread
    const int a_ub  = (lid >> 4) & 1;            // A: unit low bit
    const int b_ub  = (lid >> 3) & 1;            // B: unit low bit
    const uint32_t a_row_off =
        (uint32_t)((w * 32 + ((lid >> 3) & 1) * 8 + lrow8) * ROW_BYTES);
    const uint32_t b_row_off =
        (uint32_t)(B_OFF + lrow8 * ROW_BYTES);

    float acc[2][4][4];            // [mtile16][ntile8][frag]
#pragma unroll
    for (int a = 0; a < 2; a++)
#pragma unroll
        for (int b2 = 0; b2 < 4; b2++)
#pragma unroll
            for (int c = 0; c < 4; c++) acc[a][b2][c] = 0.0f;

    int slot = 0;                  // = t % 3
    int lslot = S_STAGES - 1;      // = (t+2) % 3
    for (int t = 0; t < T_CHUNKS; t++) {
        CP_WAIT1();                // chunk t complete (1 newer group may pend)
        __syncthreads();           // all warps done with the slot being refilled

        const int lk = t + S_STAGES - 1;
        if (lk < T_CHUNKS) {
            load_stage_A(sbase, G, lslot, lk, mtile, tid);
            load_stage_B(sbase, B, lslot, lk, tid);
        }
        CP_COMMIT();               // commit every iter (possibly empty group)

        const uint32_t st = sbase + slot * STAGE_BYTES;
        const uint32_t a_base = st + a_row_off;
        const uint32_t b_base = st + b_row_off;

#pragma unroll
        for (int k0 = 0; k0 < 8; k0++) {   // 8 k-steps of 8 (1 unit pair each)
            const uint32_t au = (uint32_t)(((k0 * 2 + a_ub) ^ lrow8) << 4);
            const uint32_t bu = (uint32_t)(((k0 * 2 + b_ub) ^ lrow8) << 4);
            uint32_t bf[4][2];
#pragma unroll
            for (int nt = 0; nt < 4; nt++)
                LDSM_X2(bf[nt][0], bf[nt][1], b_base + nt * (8 * ROW_BYTES) + bu);
#pragma unroll
            for (int mt = 0; mt < 2; mt++) {
                uint32_t a0, a1, a2, a3;
                LDSM_X4(a0, a1, a2, a3, a_base + mt * (16 * ROW_BYTES) + au);
#pragma unroll
                for (int nt = 0; nt < 4; nt++)
                    mma_tf32(acc[mt][nt][0], acc[mt][nt][1], acc[mt][nt][2], acc[mt][nt][3],
                             a0, a1, a2, a3, bf[nt][0], bf[nt][1]);
            }
        }
        slot = (slot == S_STAGES - 1) ? 0 : slot + 1;
        lslot = (lslot == S_STAGES - 1) ? 0 : lslot + 1;
    }

    // Epilogue: c-frag m16n8: thread holds rows l4, l4+8; cols 2*lm, 2*lm+1
    float* P = g_partial + (size_t)branch * 8192 * 32;
#pragma unroll
    for (int mt = 0; mt < 2; mt++) {
        const int r0 = mtile * M_TILE + w * 32 + mt * 16 + l4;
#pragma unroll
        for (int nt = 0; nt < 4; nt++) {
            const int col = nt * 8 + lm * 2;
            float2* d0 = reinterpret_cast<float2*>(P + (size_t)r0 * 32 + col);
            float2* d1 = reinterpret_cast<float2*>(P + (size_t)(r0 + 8) * 32 + col);
            *d0 = make_float2(acc[mt][nt][0], acc[mt][nt][1]);
            *d1 = make_float2(acc[mt][nt][2], acc[mt][nt][3]);
        }
    }
}

// ============================================================================
// Reduce 4 partials + relu -> out[8192,32] f32. Also resets prep flags
// (stream-ordered after the GEMM -> race-free, graph-replay safe).
// ============================================================================
__global__ void reduce_relu_kernel(float4* __restrict__ out)
{
    if (blockIdx.x == 0 && threadIdx.x < 128) g_flag[threadIdx.x] = 0u;

    const int i = blockIdx.x * blockDim.x + threadIdx.x;     // 0..65535 float4s
    const float4* p = reinterpret_cast<const float4*>(g_partial);
    float4 a = p[i], b = p[i + 65536], c = p[i + 131072], d = p[i + 196608];
    float4 r;
    r.x = fmaxf(a.x + b.x + c.x + d.x, 0.0f);
    r.y = fmaxf(a.y + b.y + c.y + d.y, 0.0f);
    r.z = fmaxf(a.z + b.z + c.z + d.z, 0.0f);
    r.w = fmaxf(a.w + b.w + c.w + d.w, 0.0f);
    out[i] = r;
}

// ============================================================================
// Launch
// ============================================================================
extern "C" void kernel_launch(void* const* d_in, const int* in_sizes, int n_in,
                              void* d_out, int out_size)
{
    const float* xi  = (const float*)d_in[0];
    const float* xj1 = (const float*)d_in[1];
    const float* xk  = (const float*)d_in[3];
    const float* Gi  = (const float*)d_in[4];
    const float* Ad  = (const float*)d_in[5];
    const float* co  = (const float*)d_in[6];
    const float* Gk  = (const float*)d_in[7];

    cudaFuncSetAttribute(gemm_tf32_kernel,
                         cudaFuncAttributeMaxDynamicSharedMemorySize, SMEM_TOTAL);
    cudaFuncSetAttribute(gemm_tf32_kernel,
                         cudaFuncAttributePreferredSharedMemoryCarveout, 100);

    gemm_tf32_kernel<<<dim3(32, 4), 256, SMEM_TOTAL>>>(
        Gi, Ad, co, Gk,
        xi, xj1, xk,
        (const float*)d_in[8],  (const float*)d_in[9],
        (const float*)d_in[10], (const float*)d_in[11],
        (const float*)d_in[12], (const float*)d_in[13],
        (const float*)d_in[14], (const float*)d_in[15]);

    reduce_relu_kernel<<<256, 256>>>((float4*)d_out);
}

// round 12
// speedup vs baseline: 1.0274x; 1.0274x over previous
#include <cuda_runtime.h>
#include <cstdint>
#include <cstddef>

// ============================================================================
//   z[8192,32] = relu( Gi2j@(xi Wi+bi) + Adj2j@(xj1 Wj1+bj1)
//                    + coAdj2j@(xj1 Wj2+bj2) + Gk2j@(xk Wk+bk) )
// Inputs (metadata order):
//   0 xi, 1 xj1, 2 xj2(unused), 3 xk, 4 Gi2j, 5 Adj2j, 6 coAdj2j, 7 Gk2j,
//   8..11 W_i,W_j1,W_j2,W_k, 12..15 b_i,b_j1,b_j2,b_k
//
// Bench PTX target is plain sm_103 (no 'a' features): no tcgen05/TMEM.
// R12: R10 fused kernel, but the x LDGs are issued BEFORE the A cp.asyncs
// (L1tex FIFO order), so the prep FFMA + flag handshake overlap the first
// 144KB of A DRAM fetch instead of serializing in front of it (R11 bug).
// ============================================================================

// Scratch (allocation-free: __device__ globals; zero-initialized at load)
__device__ float g_B[4 * 32 * 8192];        // [branch][c][k]  (Y_m^T, k-contiguous)
__device__ float g_partial[4 * 8192 * 32];  // [branch][j][c]
__device__ unsigned int g_flag[128];        // [branch*32 + mtile] B-slice ready

__device__ __forceinline__ uint32_t smem_u32(const void* p) {
    uint32_t a;
    asm("{ .reg .u64 t; cvta.to.shared.u64 t, %1; cvt.u32.u64 %0, t; }" : "=r"(a) : "l"(p));
    return a;
}

#define CP_ASYNC16(dst, src) \
    asm volatile("cp.async.cg.shared.global [%0], [%1], 16;" :: "r"(dst), "l"(src) : "memory")
#define CP_COMMIT() asm volatile("cp.async.commit_group;" ::: "memory")
#define CP_WAIT1()  asm volatile("cp.async.wait_group 1;" ::: "memory")
#define CP_WAIT0()  asm volatile("cp.async.wait_group 0;" ::: "memory")

// ldmatrix: b16 view over fp32 data (each b16-pair = one fp32 element).
#define LDSM_X4(r0, r1, r2, r3, addr) \
    asm volatile("ldmatrix.sync.aligned.m8n8.x4.shared.b16 {%0,%1,%2,%3}, [%4];" \
        : "=r"(r0), "=r"(r1), "=r"(r2), "=r"(r3) : "r"(addr))
#define LDSM_X2(r0, r1, addr) \
    asm volatile("ldmatrix.sync.aligned.m8n8.x2.shared.b16 {%0,%1}, [%2];" \
        : "=r"(r0), "=r"(r1) : "r"(addr))

__device__ __forceinline__ void mma_tf32(float& c0, float& c1, float& c2, float& c3,
                                         uint32_t a0, uint32_t a1, uint32_t a2, uint32_t a3,
                                         uint32_t b0, uint32_t b1) {
    asm volatile(
        "mma.sync.aligned.m16n8k8.row.col.f32.tf32.tf32.f32 "
        "{%0,%1,%2,%3}, {%4,%5,%6,%7}, {%8,%9}, {%0,%1,%2,%3};"
        : "+f"(c0), "+f"(c1), "+f"(c2), "+f"(c3)
        : "r"(a0), "r"(a1), "r"(a2), "r"(a3), "r"(b0), "r"(b1));
}

// ============================================================================
// Fused prep + tf32 mma.sync GEMM
//   grid (32 M-tiles, 4 branches), 256 threads (8 warps; warp = m32 x n32).
// ============================================================================
#define M_TILE  256
#define S_STAGES 3
#define T_CHUNKS 128                 // 8192 / 64
#define ROW_BYTES 256                // 64 floats, no pad
#define A_BYTES (M_TILE * ROW_BYTES)          // 65536
#define B_OFF   A_BYTES
#define STAGE_BYTES (A_BYTES + 32 * ROW_BYTES)  // 73728
#define RING_BYTES (S_STAGES * STAGE_BYTES)     // 221184
#define PREP_OFF  RING_BYTES                    // Ws(4096) + bs(128)
#define SMEM_TOTAL (RING_BYTES + 4096 + 128)    // 225408 B (1 CTA/SM)

__device__ __forceinline__ void load_stage_A(uint32_t sbase, const float* __restrict__ G,
                                             int slot, int kchunk, int mtile, int tid)
{
    const int kbase = kchunk * 64;
    const uint32_t st = sbase + slot * STAGE_BYTES;
#pragma unroll
    for (int i = 0; i < 16; i++) {
        int ch = tid + i * 256;              // 0..4095
        int r = ch >> 4, u = ch & 15;
        uint32_t dst = st + r * ROW_BYTES + ((u ^ (r & 7)) << 4);
        const float* src = G + (size_t)(mtile * M_TILE + r) * 8192 + kbase + u * 4;
        CP_ASYNC16(dst, src);
    }
}

__device__ __forceinline__ void load_stage_B(uint32_t sbase, const float* __restrict__ B,
                                             int slot, int kchunk, int tid)
{
    const int kbase = kchunk * 64;
    const uint32_t st = sbase + slot * STAGE_BYTES;
#pragma unroll
    for (int i = 0; i < 2; i++) {
        int ch = tid + i * 256;              // 0..511
        int r = ch >> 4, u = ch & 15;
        uint32_t dst = st + B_OFF + r * ROW_BYTES + ((u ^ (r & 7)) << 4);
        const float* src = B + (size_t)r * 8192 + kbase + u * 4;
        CP_ASYNC16(dst, src);
    }
}

__global__ void __launch_bounds__(256, 1)
gemm_tf32_kernel(const float* __restrict__ G0, const float* __restrict__ G1,
                 const float* __restrict__ G2, const float* __restrict__ G3,
                 const float* __restrict__ xi, const float* __restrict__ xj1,
                 const float* __restrict__ xk,
                 const float* __restrict__ Wi, const float* __restrict__ Wj1,
                 const float* __restrict__ Wj2, const float* __restrict__ Wk,
                 const float* __restrict__ bi, const float* __restrict__ bj1,
                 const float* __restrict__ bj2, const float* __restrict__ bk)
{
    extern __shared__ __align__(256) char smem[];
    const uint32_t sbase = smem_u32(smem);
    const int tid = threadIdx.x;
    const int w = tid >> 5;        // 0..7 (warp owns rows w*32..w*32+31)
    const int lid = tid & 31;
    const int l4 = lid >> 2;       // 0..7
    const int lm = lid & 3;        // 0..3
    const int mtile = blockIdx.x;
    const int branch = blockIdx.y;
    const float* __restrict__ G =
        (branch == 0) ? G0 : (branch == 1) ? G1 : (branch == 2) ? G2 : G3;
    float* __restrict__ Bbr = g_B + (size_t)branch * 32 * 8192;

    // ---------------- Phase 0: prep overlapped with A prologue ----------------
    {
        // branch 2 consumes xj1 with the j2 weights (faithful to source)
        const float* x = (branch == 0) ? xi : (branch == 3) ? xk : xj1;
        const float* W = (branch == 0) ? Wi : (branch == 1) ? Wj1
                         : (branch == 2) ? Wj2 : Wk;
        const float* b = (branch == 0) ? bi : (branch == 1) ? bj1
                         : (branch == 2) ? bj2 : bk;

        float* Ws = reinterpret_cast<float*>(smem + PREP_OFF);        // 1024 f
        float* bs = reinterpret_cast<float*>(smem + PREP_OFF) + 1024; // 32 f
#pragma unroll
        for (int i = 0; i < 4; i++) Ws[tid + i * 256] = W[tid + i * 256];
        if (tid < 32) bs[tid] = b[tid];

        // x LDGs FIRST — they sit ahead of the cp.asyncs in the L1tex FIFO.
        const int k = mtile * 256 + tid;     // this thread's k-row
        float xr[32];
        const float4* xrow = reinterpret_cast<const float4*>(x + (size_t)k * 32);
#pragma unroll
        for (int t = 0; t < 8; t++) {
            float4 v = xrow[t];
            xr[4 * t] = v.x; xr[4 * t + 1] = v.y; xr[4 * t + 2] = v.z; xr[4 * t + 3] = v.w;
        }

        // NOW start the A DRAM stream for stages 0,1 (overlaps prep compute).
        load_stage_A(sbase, G, 0, 0, mtile, tid);
        CP_COMMIT();
        load_stage_A(sbase, G, 1, 1, mtile, tid);
        CP_COMMIT();

        __syncthreads();           // Ws/bs visible

        float acc[32];
#pragma unroll
        for (int c = 0; c < 32; c++) acc[c] = bs[c];
#pragma unroll
        for (int t = 0; t < 32; t++) {
            const float xv = xr[t];
#pragma unroll
            for (int c = 0; c < 32; c++) acc[c] += xv * Ws[t * 32 + c];
        }
#pragma unroll
        for (int c = 0; c < 32; c++) {
            uint32_t v = __float_as_uint(acc[c]);
            asm volatile("cvt.rna.tf32.f32 %0, %0;" : "+r"(v));  // pre-round B
            Bbr[(size_t)c * 8192 + k] = __uint_as_float(v);      // coalesced in k
        }

        // Publish, then wait for all 32 slices of this branch.
        __threadfence();
        __syncthreads();
        if (tid == 0) atomicExch(&g_flag[branch * 32 + mtile], 1u);
        if (tid < 32) {
            while (atomicAdd(&g_flag[branch * 32 + tid], 0u) == 0u) { __nanosleep(64); }
        }
        __syncthreads();
        __threadfence();   // acquire side: B stores from other CTAs visible
    }

    // ---- B fetches for stages 0,1 (small; mostly L2 hits), drain all ----
    const float* __restrict__ B = Bbr;
    load_stage_B(sbase, B, 0, 0, tid);
    load_stage_B(sbase, B, 1, 1, tid);
    CP_COMMIT();
    CP_WAIT0();
    __syncthreads();

    // ---------------- Phase 1: GEMM mainloop (R7-proven) ----------------
    const int lrow8 = lid & 7;                   // swizzle XOR for this thread
    const int a_ub  = (lid >> 4) & 1;            // A: unit low bit
    const int b_ub  = (lid >> 3) & 1;            // B: unit low bit
    const uint32_t a_row_off =
        (uint32_t)((w * 32 + ((lid >> 3) & 1) * 8 + lrow8) * ROW_BYTES);
    const uint32_t b_row_off =
        (uint32_t)(B_OFF + lrow8 * ROW_BYTES);

    float acc[2][4][4];            // [mtile16][ntile8][frag]
#pragma unroll
    for (int a = 0; a < 2; a++)
#pragma unroll
        for (int b2 = 0; b2 < 4; b2++)
#pragma unroll
            for (int c = 0; c < 4; c++) acc[a][b2][c] = 0.0f;

    int slot = 0;                  // = t % 3
    int lslot = S_STAGES - 1;      // = (t+2) % 3
    for (int t = 0; t < T_CHUNKS; t++) {
        CP_WAIT1();                // chunk t complete (1 newer group may pend)
        __syncthreads();           // all warps done with the slot being refilled

        const int lk = t + S_STAGES - 1;
        if (lk < T_CHUNKS) {
            load_stage_A(sbase, G, lslot, lk, mtile, tid);
            load_stage_B(sbase, B, lslot, lk, tid);
        }
        CP_COMMIT();               // commit every iter (possibly empty group)

        const uint32_t st = sbase + slot * STAGE_BYTES;
        const uint32_t a_base = st + a_row_off;
        const uint32_t b_base = st + b_row_off;

#pragma unroll
        for (int k0 = 0; k0 < 8; k0++) {   // 8 k-steps of 8 (1 unit pair each)
            const uint32_t au = (uint32_t)(((k0 * 2 + a_ub) ^ lrow8) << 4);
            const uint32_t bu = (uint32_t)(((k0 * 2 + b_ub) ^ lrow8) << 4);
            uint32_t bf[4][2];
#pragma unroll
            for (int nt = 0; nt < 4; nt++)
                LDSM_X2(bf[nt][0], bf[nt][1], b_base + nt * (8 * ROW_BYTES) + bu);
#pragma unroll
            for (int mt = 0; mt < 2; mt++) {
                uint32_t a0, a1, a2, a3;
                LDSM_X4(a0, a1, a2, a3, a_base + mt * (16 * ROW_BYTES) + au);
#pragma unroll
                for (int nt = 0; nt < 4; nt++)
                    mma_tf32(acc[mt][nt][0], acc[mt][nt][1], acc[mt][nt][2], acc[mt][nt][3],
                             a0, a1, a2, a3, bf[nt][0], bf[nt][1]);
            }
        }
        slot = (slot == S_STAGES - 1) ? 0 : slot + 1;
        lslot = (lslot == S_STAGES - 1) ? 0 : lslot + 1;
    }

    // Epilogue: c-frag m16n8: thread holds rows l4, l4+8; cols 2*lm, 2*lm+1
    float* P = g_partial + (size_t)branch * 8192 * 32;
#pragma unroll
    for (int mt = 0; mt < 2; mt++) {
        const int r0 = mtile * M_TILE + w * 32 + mt * 16 + l4;
#pragma unroll
        for (int nt = 0; nt < 4; nt++) {
            const int col = nt * 8 + lm * 2;
            float2* d0 = reinterpret_cast<float2*>(P + (size_t)r0 * 32 + col);
            float2* d1 = reinterpret_cast<float2*>(P + (size_t)(r0 + 8) * 32 + col);
            *d0 = make_float2(acc[mt][nt][0], acc[mt][nt][1]);
            *d1 = make_float2(acc[mt][nt][2], acc[mt][nt][3]);
        }
    }
}

// ============================================================================
// Reduce 4 partials + relu -> out[8192,32] f32. Also resets prep flags
// (stream-ordered after the GEMM -> race-free, graph-replay safe).
// ============================================================================
__global__ void reduce_relu_kernel(float4* __restrict__ out)
{
    if (blockIdx.x == 0 && threadIdx.x < 128) g_flag[threadIdx.x] = 0u;

    const int i = blockIdx.x * blockDim.x + threadIdx.x;     // 0..65535 float4s
    const float4* p = reinterpret_cast<const float4*>(g_partial);
    float4 a = p[i], b = p[i + 65536], c = p[i + 131072], d = p[i + 196608];
    float4 r;
    r.x = fmaxf(a.x + b.x + c.x + d.x, 0.0f);
    r.y = fmaxf(a.y + b.y + c.y + d.y, 0.0f);
    r.z = fmaxf(a.z + b.z + c.z + d.z, 0.0f);
    r.w = fmaxf(a.w + b.w + c.w + d.w, 0.0f);
    out[i] = r;
}

// ============================================================================
// Launch
// ============================================================================
extern "C" void kernel_launch(void* const* d_in, const int* in_sizes, int n_in,
                              void* d_out, int out_size)
{
    const float* xi  = (const float*)d_in[0];
    const float* xj1 = (const float*)d_in[1];
    const float* xk  = (const float*)d_in[3];
    const float* Gi  = (const float*)d_in[4];
    const float* Ad  = (const float*)d_in[5];
    const float* co  = (const float*)d_in[6];
    const float* Gk  = (const float*)d_in[7];

    cudaFuncSetAttribute(gemm_tf32_kernel,
                         cudaFuncAttributeMaxDynamicSharedMemorySize, SMEM_TOTAL);
    cudaFuncSetAttribute(gemm_tf32_kernel,
                         cudaFuncAttributePreferredSharedMemoryCarveout, 100);

    gemm_tf32_kernel<<<dim3(32, 4), 256, SMEM_TOTAL>>>(
        Gi, Ad, co, Gk,
        xi, xj1, xk,
        (const float*)d_in[8],  (const float*)d_in[9],
        (const float*)d_in[10], (const float*)d_in[11],
        (const float*)d_in[12], (const float*)d_in[13],
        (const float*)d_in[14], (const float*)d_in[15]);

    reduce_relu_kernel<<<256, 256>>>((float4*)d_out);
}